// round 7
// baseline (speedup 1.0000x reference)
#include <cuda_runtime.h>
#include <math.h>
#include <float.h>

#define B 64
#define C 32
#define HH 16
#define WW 16
#define VOCAB 4096
#define NPIX (B*HH*WW)          // 16384
#define NELEM (NPIX*C)          // 524288
#define NROWS_TOT 43520         // sum of N over all 10 scales
#define NBLK 296                // 2 blocks/SM on 148 SMs -> guaranteed co-resident
typedef unsigned long long ull;

// ---------------- device scratch (static, no allocations) ----------------
__device__ float  g_frest[NELEM];          // residual, BHWC
__device__ float  g_fhat [NELEM];          // accumulator, BHWC
__device__ float  g_z    [64*13*13*32];    // pooled z (largest non-last scale)
__device__ float  g_tmp  [64*16*13*32];    // H-interp intermediate [b][oh][iw][c]
__device__ ull    g_best [NROWS_TOT];      // packed (ordered-score<<32)|idx, all scales
__device__ float  g_esq  [VOCAB];          // ||e_j||^2 (reference rounding order)
__device__ float  g_emb2 [VOCAB*C];        // pair-interleaved codebook: [j/2][c][2]
__device__ int    g_upi  [9][16];          // cubic tap start index per (scale, out-pos)
__device__ float  g_upw  [9][16][4];       // cubic tap weights  per (scale, out-pos)
__device__ unsigned g_count;               // barrier arrival counter (self-resetting)
__device__ unsigned g_gen;                 // barrier generation (monotone across replays)

__constant__ int c_PNS [10] = {1,2,3,4,5,6,8,10,13,16};
__constant__ int c_CH  [10] = {64,64,64,64,32,32,16,8,4,4};
__constant__ int c_BASE[10] = {0,64,320,896,1920,3520,5824,9920,16320,27136};

// ---------------- grid-wide barrier (all NBLK blocks co-resident) ----------------
__device__ __forceinline__ void gsync(unsigned &gen) {
    __syncthreads();
    if (threadIdx.x == 0) {
        unsigned target = gen + 1u;
        __threadfence();
        if (atomicAdd(&g_count, 1u) == gridDim.x - 1u) {
            g_count = 0u;
            asm volatile("st.release.gpu.u32 [%0], %1;" :: "l"(&g_gen), "r"(target) : "memory");
        } else {
            unsigned v;
            do {
                asm volatile("ld.acquire.gpu.u32 %0, [%1];" : "=r"(v) : "l"(&g_gen) : "memory");
            } while (v != target);
        }
    }
    __syncthreads();
    gen = gen + 1u;
}

// Keys cubic kernel (a = -0.5), matching jax _fill_keys_cubic_kernel, fp32 ops
__device__ __forceinline__ float keys_cubic(float x) {
    if (x >= 2.f) return 0.f;
    if (x >= 1.f) return ((-0.5f*x + 2.5f)*x - 4.f)*x + 2.f;
    return ((1.5f*x - 2.5f)*x)*x + 1.f;
}

// ---------------- argmin unit: 256 rows x one vocab chunk ----------------
// Per-code distance chain is a single sequential fp32 fma chain ascending c
// (each f32x2 lane is an exact fp32 fma) -> bit-identical to reference.
// Cross-chunk reduce: atomicMin on key=(ordered_score<<32)|idx == first-min rule.
__device__ __forceinline__ void argmin_unit(
    float (&s_e)[2][2112], const float* zsrc, int N, int base,
    int rb, int ch, int cpc, int tid, int lane, int wid)
{
    int row = rb * 256 + wid * 32 + lane;

    float zf[C];
    if (row < N) {
        const float4* z4 = (const float4*)(zsrc + (size_t)row * C);
        #pragma unroll
        for (int k = 0; k < 8; k++) {
            float4 v = __ldcg(z4 + k);          // L2 path: frest/z written by other blocks
            zf[4*k] = v.x; zf[4*k+1] = v.y; zf[4*k+2] = v.z; zf[4*k+3] = v.w;
        }
    } else {
        #pragma unroll
        for (int k = 0; k < C; k++) zf[k] = 0.f;
    }
    float z2 = 0.f;
    #pragma unroll
    for (int k = 0; k < C; k++) z2 = __fadd_rn(z2, __fmul_rn(zf[k], zf[k]));
    ull zz[C];
    #pragma unroll
    for (int k = 0; k < C; k++)
        asm("mov.b64 %0, {%1, %2};" : "=l"(zz[k]) : "f"(zf[k]), "f"(zf[k]));

    int code0 = ch * cpc;
    int T = cpc >> 6;                       // tiles of 64 codes
    float best = FLT_MAX; int bj = 0;

    __syncthreads();                        // smem reuse guard vs previous unit
    {   // prime tile 0
        const float4* src = (const float4*)(g_emb2 + (size_t)code0 * C);
        float4* dst = (float4*)s_e[0];
        dst[tid]       = src[tid];
        dst[256 + tid] = src[256 + tid];
        if (tid < 16)
            ((float4*)(s_e[0] + 2048))[tid] = ((const float4*)(g_esq + code0))[tid];
    }

    for (int t = 0; t < T; t++) {
        __syncthreads();
        if (t + 1 < T) {
            int cb = code0 + (t + 1) * 64;
            const float4* src = (const float4*)(g_emb2 + (size_t)cb * C);
            float4* dst = (float4*)s_e[(t + 1) & 1];
            dst[tid]       = src[tid];
            dst[256 + tid] = src[256 + tid];
            if (tid < 16)
                ((float4*)(s_e[(t + 1) & 1] + 2048))[tid] =
                    ((const float4*)(g_esq + cb))[tid];
        }
        int bsel = t & 1;
        unsigned sbase = (unsigned)__cvta_generic_to_shared(s_e[bsel]);
        const float* se = s_e[bsel] + 2048;
        #pragma unroll 1
        for (int p = 0; p < 32; p += 4) {   // 4 code-pairs (8 codes) in flight
            ull acc[4]; acc[0]=0ULL; acc[1]=0ULL; acc[2]=0ULL; acc[3]=0ULL;
            unsigned ab = sbase + (unsigned)p * 256u;
            #pragma unroll
            for (int c = 0; c < C; c += 2) {
                ull u0[4], u1[4];
                #pragma unroll
                for (int i = 0; i < 4; i++)
                    asm volatile("ld.shared.v2.b64 {%0,%1}, [%2];"
                                 : "=l"(u0[i]), "=l"(u1[i])
                                 : "r"(ab + (unsigned)i * 256u + (unsigned)c * 8u));
                #pragma unroll
                for (int i = 0; i < 4; i++)   // same-chain FMAs 4 instrs apart
                    asm("fma.rn.f32x2 %0, %1, %2, %0;" : "+l"(acc[i]) : "l"(zz[c]),   "l"(u0[i]));
                #pragma unroll
                for (int i = 0; i < 4; i++)
                    asm("fma.rn.f32x2 %0, %1, %2, %0;" : "+l"(acc[i]) : "l"(zz[c+1]), "l"(u1[i]));
            }
            int jb = code0 + t * 64 + 2 * p;
            #pragma unroll
            for (int i = 0; i < 4; i++) {
                float lo, hi;
                asm("mov.b64 {%0,%1}, %2;" : "=f"(lo), "=f"(hi) : "l"(acc[i]));
                float s0 = __fadd_rn(__fadd_rn(z2, se[2*p + 2*i    ]), __fmul_rn(-2.f, lo));
                float s1 = __fadd_rn(__fadd_rn(z2, se[2*p + 2*i + 1]), __fmul_rn(-2.f, hi));
                if (s0 < best) { best = s0; bj = jb + 2*i;     }
                if (s1 < best) { best = s1; bj = jb + 2*i + 1; }
            }
        }
    }
    if (row < N) {
        unsigned sb = __float_as_uint(best);
        sb = (sb & 0x80000000u) ? ~sb : (sb | 0x80000000u);   // monotone float->uint
        ull key = ((ull)sb << 32) | (unsigned)bj;
        atomicMin(&g_best[base + row], key);
    }
}

// ---------------- the whole pipeline in ONE persistent kernel ----------------
__global__ void __launch_bounds__(256, 2)
k_mega(const float* __restrict__ f, const float* __restrict__ emb, float* __restrict__ out)
{
    __shared__ float s_e[2][2112];
    unsigned gen;
    asm volatile("ld.acquire.gpu.u32 %0, [%1];" : "=r"(gen) : "l"(&g_gen) : "memory");
    const int tid = threadIdx.x;
    const int lane = tid & 31, wid = tid >> 5;

    // ===== phase 0: init (transpose, fhat=0, best=~0, esq, emb2, cubic tables) =====
    for (unsigned u = blockIdx.x; u < 512; u += gridDim.x) {
        int t = (int)u * 256 + tid;
        {
            int c4 = t & 7; int w = (t >> 3) & 15; int h = (t >> 7) & 15; int b = t >> 11;
            const float* fp = f + ((size_t)b*C + c4*4)*256 + h*WW + w;
            ((float4*)g_frest)[t] = make_float4(fp[0], fp[256], fp[512], fp[768]);
            ((float4*)g_fhat)[t]  = make_float4(0.f, 0.f, 0.f, 0.f);
        }
        if (t < NROWS_TOT) g_best[t] = ~0ULL;
        if (t < VOCAB) {
            float s = 0.f;
            int half = t & 1, pairbase = (t >> 1) * 64;
            #pragma unroll
            for (int c = 0; c < C; c++) {
                float v = emb[(size_t)t * C + c];
                s = __fadd_rn(s, __fmul_rn(v, v));
                g_emb2[pairbase + c * 2 + half] = v;
            }
            g_esq[t] = s;
        }
        if (t < 9 * 16) {
            int si = t >> 4, o = t & 15;
            int pn = c_PNS[si];
            float sf = ((float)o + 0.5f) * ((float)pn / 16.0f) - 0.5f;
            int i0 = (int)floorf(sf) - 1;
            float w[4]; float s = 0.f;
            #pragma unroll
            for (int a = 0; a < 4; a++) {
                int i = i0 + a;
                float wv = 0.f;
                if (i >= 0 && i < pn) wv = keys_cubic(fabsf(sf - (float)i));
                w[a] = wv; s += wv;
            }
            float inv = (fabsf(s) > 1000.f * 1.1920929e-07f) ? 1.f / s : 0.f;
            g_upi[si][o] = i0;
            #pragma unroll
            for (int a = 0; a < 4; a++) g_upw[si][o][a] = w[a] * inv;
        }
    }
    gsync(gen);

    for (int si = 0; si < 10; si++) {
        int pn = c_PNS[si], N = B * pn * pn, base = c_BASE[si];
        bool last = (si == 9);

        // ===== pool: frest -> z (H inner, W outer — einsum order) =====
        if (!last) {
            int tot = N * 8;
            unsigned ptiles = (unsigned)((tot + 255) >> 8);
            for (unsigned u = blockIdx.x; u < ptiles; u += gridDim.x) {
                int t = (int)u * 256 + tid;
                if (t < tot) {
                    int c4 = t & 7; int n = t >> 3;
                    int q = n % pn; int m = n / pn; int p = m % pn; int b = m / pn;
                    int h0 = (p*HH)/pn,  h1 = ((p+1)*HH + pn - 1)/pn;
                    int w0 = (q*WW)/pn,  w1 = ((q+1)*WW + pn - 1)/pn;
                    float wh = 1.0f / (float)(h1 - h0);
                    float ww = 1.0f / (float)(w1 - w0);
                    float4 acc = make_float4(0.f,0.f,0.f,0.f);
                    for (int w = w0; w < w1; w++) {
                        float4 th = make_float4(0.f,0.f,0.f,0.f);
                        for (int h = h0; h < h1; h++) {
                            float4 v = __ldcg((const float4*)g_frest + ((b*HH + h)*WW + w)*8 + c4);
                            th.x = fmaf(wh, v.x, th.x); th.y = fmaf(wh, v.y, th.y);
                            th.z = fmaf(wh, v.z, th.z); th.w = fmaf(wh, v.w, th.w);
                        }
                        acc.x = fmaf(ww, th.x, acc.x); acc.y = fmaf(ww, th.y, acc.y);
                        acc.z = fmaf(ww, th.z, acc.z); acc.w = fmaf(ww, th.w, acc.w);
                    }
                    ((float4*)g_z)[t] = acc;
                }
            }
            gsync(gen);
        }

        // ===== argmin =====
        {
            int CH = c_CH[si], cpc = VOCAB / CH;
            int RB = (N + 255) >> 8;
            unsigned units = (unsigned)(RB * CH);
            const float* zsrc = last ? g_frest : g_z;
            for (unsigned u = blockIdx.x; u < units; u += gridDim.x) {
                int rb = (int)(u / (unsigned)CH);
                int ch = (int)(u % (unsigned)CH);
                argmin_unit(s_e, zsrc, N, base, rb, ch, cpc, tid, lane, wid);
            }
        }
        gsync(gen);

        if (!last) {
            // ===== update pass 1: H-interp gather -> g_tmp[b][oh][iw][c] =====
            int E1 = B * 16 * pn * 8;
            unsigned t1 = (unsigned)((E1 + 255) >> 8);
            for (unsigned u = blockIdx.x; u < t1; u += gridDim.x) {
                int t = (int)u * 256 + tid;
                if (t < E1) {
                    int c4 = t & 7; int rest = t >> 3;
                    int iw = rest % pn; int r2 = rest / pn;
                    int oh = r2 & 15; int b = r2 >> 4;
                    int ih0 = g_upi[si][oh];
                    float4 tc = make_float4(0.f,0.f,0.f,0.f);
                    #pragma unroll
                    for (int a = 0; a < 4; a++) {
                        int ih = ih0 + a;
                        if (ih < 0 || ih >= pn) continue;
                        float wh = g_upw[si][oh][a];
                        int j = (int)(unsigned)g_best[base + (b*pn + ih)*pn + iw];
                        float4 e = __ldg((const float4*)emb + (size_t)j * 8 + c4);
                        tc.x = fmaf(wh, e.x, tc.x); tc.y = fmaf(wh, e.y, tc.y);
                        tc.z = fmaf(wh, e.z, tc.z); tc.w = fmaf(wh, e.w, tc.w);
                    }
                    ((float4*)g_tmp)[t] = tc;
                }
            }
            gsync(gen);

            // ===== update pass 2: W-interp from g_tmp, fhat += h, frest -= h =====
            for (unsigned u = blockIdx.x; u < 512; u += gridDim.x) {
                int t = (int)u * 256 + tid;
                int c4 = t & 7; int ow = (t >> 3) & 15; int oh = (t >> 7) & 15; int b = t >> 11;
                int iw0 = g_upi[si][ow];
                float4 acc = make_float4(0.f,0.f,0.f,0.f);
                #pragma unroll
                for (int d = 0; d < 4; d++) {
                    int iw = iw0 + d;
                    if (iw < 0 || iw >= pn) continue;
                    float wv = g_upw[si][ow][d];
                    float4 v = __ldcg((const float4*)g_tmp + ((size_t)(b*16 + oh)*pn + iw)*8 + c4);
                    acc.x = fmaf(wv, v.x, acc.x); acc.y = fmaf(wv, v.y, acc.y);
                    acc.z = fmaf(wv, v.z, acc.z); acc.w = fmaf(wv, v.w, acc.w);
                }
                float4 fh = ((float4*)g_fhat)[t];
                float4 fr = ((float4*)g_frest)[t];
                fh.x = __fadd_rn(fh.x, acc.x); fh.y = __fadd_rn(fh.y, acc.y);
                fh.z = __fadd_rn(fh.z, acc.z); fh.w = __fadd_rn(fh.w, acc.w);
                fr.x = __fadd_rn(fr.x, -acc.x); fr.y = __fadd_rn(fr.y, -acc.y);
                fr.z = __fadd_rn(fr.z, -acc.z); fr.w = __fadd_rn(fr.w, -acc.w);
                ((float4*)g_fhat)[t]  = fh;
                ((float4*)g_frest)[t] = fr;
            }
            gsync(gen);
        } else {
            // ===== final: full-res gather + add + transpose to BCHW =====
            for (unsigned u = blockIdx.x; u < 512; u += gridDim.x) {
                int t = (int)u * 256 + tid;
                int c4 = t & 7; int w = (t >> 3) & 15; int h = (t >> 7) & 15; int b = t >> 11;
                int j = (int)(unsigned)g_best[base + (b*HH + h)*WW + w];
                float4 fh = ((float4*)g_fhat)[t];
                float4 e  = __ldg((const float4*)emb + (size_t)j * 8 + c4);
                float* op = out + ((size_t)b*C + c4*4)*256 + h*WW + w;
                op[0]   = __fadd_rn(fh.x, e.x);
                op[256] = __fadd_rn(fh.y, e.y);
                op[512] = __fadd_rn(fh.z, e.z);
                op[768] = __fadd_rn(fh.w, e.w);
            }
        }
    }
}

// ---------------- host: ONE launch ----------------
extern "C" void kernel_launch(void* const* d_in, const int* in_sizes, int n_in,
                              void* d_out, int out_size) {
    const float* f   = (const float*)d_in[0];
    const float* emb = (const float*)d_in[1];
    float* out = (float*)d_out;
    k_mega<<<NBLK, 256>>>(f, emb, out);
}

// round 9
// speedup vs baseline: 1.0861x; 1.0861x over previous
#include <cuda_runtime.h>
#include <math.h>
#include <float.h>

#define B 64
#define C 32
#define HH 16
#define WW 16
#define VOCAB 4096
#define NPIX (B*HH*WW)          // 16384
#define NELEM (NPIX*C)          // 524288
#define NROWS_TOT 43520         // sum of N over all 10 scales
typedef unsigned long long ull;

// ---------------- device scratch (static, no allocations) ----------------
__device__ float  g_frest[NELEM];          // residual, BHWC
__device__ float  g_fhat [NELEM];          // accumulator, BHWC
__device__ float  g_z    [64*13*13*32];    // pooled z (largest non-last scale)
__device__ ull    g_best [NROWS_TOT];      // packed (ordered-score<<32)|idx, all scales
__device__ ull    g_embd [VOCAB*C];        // duplicated codebook: (e_jc, e_jc) per channel
__device__ ull    g_esqd [VOCAB];          // duplicated ||e_j||^2 (reference rounding)
__device__ int    g_upi  [9][16];          // cubic tap start index per (scale, out-pos)
__device__ float  g_upw  [9][16][4];       // cubic tap weights  per (scale, out-pos)

__device__ __constant__ int d_PNS[10] = {1,2,3,4,5,6,8,10,13,16};

__device__ __forceinline__ ull pack2(float lo, float hi) {
    ull r; asm("mov.b64 %0, {%1, %2};" : "=l"(r) : "f"(lo), "f"(hi)); return r;
}

// Keys cubic kernel (a = -0.5), matching jax _fill_keys_cubic_kernel, fp32 ops
__device__ __forceinline__ float keys_cubic(float x) {
    if (x >= 2.f) return 0.f;
    if (x >= 1.f) return ((-0.5f*x + 2.5f)*x - 4.f)*x + 2.f;
    return ((1.5f*x - 2.5f)*x)*x + 1.f;
}

// ---------------- init: transpose + fhat=0 + best=~0 + dup codebook + esq + tables ------
__global__ void k_init(const float* __restrict__ f, const float* __restrict__ emb) {
    int t = blockIdx.x * blockDim.x + threadIdx.x;      // 131072 threads
    {
        int c4 = t & 7; int w = (t >> 3) & 15; int h = (t >> 7) & 15; int b = t >> 11;
        const float* fp = f + ((size_t)b*C + c4*4)*256 + h*WW + w;
        ((float4*)g_frest)[t] = make_float4(fp[0], fp[256], fp[512], fp[768]);
        ((float4*)g_fhat)[t]  = make_float4(0.f, 0.f, 0.f, 0.f);
    }
    if (t < NROWS_TOT) g_best[t] = ~0ULL;
    if (t < VOCAB) {
        float s = 0.f;
        #pragma unroll
        for (int c = 0; c < C; c++) {
            float v = emb[(size_t)t * C + c];
            s = __fadd_rn(s, __fmul_rn(v, v));          // reference rounding order
            g_embd[(size_t)t * C + c] = pack2(v, v);
        }
        g_esqd[t] = pack2(s, s);
    }
    if (t < 9 * 16) {
        int si = t >> 4, o = t & 15;
        int pn = d_PNS[si];
        float sf = ((float)o + 0.5f) * ((float)pn / 16.0f) - 0.5f;
        int i0 = (int)floorf(sf) - 1;
        float w[4]; float s = 0.f;
        #pragma unroll
        for (int a = 0; a < 4; a++) {
            int i = i0 + a;
            float wv = 0.f;
            if (i >= 0 && i < pn) wv = keys_cubic(fabsf(sf - (float)i));
            w[a] = wv; s += wv;
        }
        float inv = (fabsf(s) > 1000.f * 1.1920929e-07f) ? 1.f / s : 0.f;
        g_upi[si][o] = i0;
        #pragma unroll
        for (int a = 0; a < 4; a++) g_upw[si][o][a] = w[a] * inv;
    }
}

// ---------------- fused area pool, float4 channels (H inner, W outer — einsum order) ----
__global__ void k_pool(int pn, int total /* = N*8 */) {
    int t = blockIdx.x * blockDim.x + threadIdx.x;
    if (t >= total) return;
    int c4 = t & 7; int n = t >> 3;
    int q = n % pn; int tmp = n / pn; int p = tmp % pn; int b = tmp / pn;
    int h0 = (p*HH)/pn,  h1 = ((p+1)*HH + pn - 1)/pn;
    int w0 = (q*WW)/pn,  w1 = ((q+1)*WW + pn - 1)/pn;
    float wh = 1.0f / (float)(h1 - h0);
    float ww = 1.0f / (float)(w1 - w0);
    float4 acc = make_float4(0.f,0.f,0.f,0.f);
    for (int w = w0; w < w1; w++) {
        float4 th = make_float4(0.f,0.f,0.f,0.f);
        for (int h = h0; h < h1; h++) {
            float4 v = ((const float4*)g_frest)[((b*HH + h)*WW + w)*8 + c4];
            th.x = fmaf(wh, v.x, th.x); th.y = fmaf(wh, v.y, th.y);
            th.z = fmaf(wh, v.z, th.z); th.w = fmaf(wh, v.w, th.w);
        }
        acc.x = fmaf(ww, th.x, acc.x); acc.y = fmaf(ww, th.y, acc.y);
        acc.z = fmaf(ww, th.z, acc.z); acc.w = fmaf(ww, th.w, acc.w);
    }
    ((float4*)g_z)[t] = acc;
}

// ---------------- argmin: 4 rows x 4 codes per thread, duplicated-code smem tiles -------
// f32x2 lanes hold TWO DIFFERENT ROWS; code channels streamed duplicated (e_c,e_c).
// One 16B LDS feeds 4 FFMA2 -> LDS:FMA2 = 1:4. Each row's dot is a single sequential
// fp32 fma chain ascending c (its lane) -> bit-identical to reference rounding.
// Score: t = add.f32x2(z2pair, esqdup); s = fma.f32x2(acc, -2, t)  ==  fl(fl(z2+esq)-2*dot).
// Cross-chunk reduce: atomicMin on key=(ordered_score<<32)|idx == first-min tie rule.
__global__ void __launch_bounds__(256, 1) k_argmin(int N, int useFrest, int cpc, int base) {
    __shared__ ull s_d[2][2048];           // 64 codes x 32 duplicated channels
    __shared__ ull s_q[2][64];             // duplicated esq per code
    const float* zsrc = useFrest ? g_frest : g_z;
    const int tid = threadIdx.x;
    const int r0 = blockIdx.x * 1024 + tid;   // rows r0 + k*256, k=0..3

    // load 4 z rows; compute z2 (reference order); pack row pairs
    ull zzA[C], zzB[C];
    ull z2A, z2B;
    {
        float a[C], b[C];
        float z2[4];
        #pragma unroll
        for (int pr = 0; pr < 2; pr++) {
            #pragma unroll
            for (int half = 0; half < 2; half++) {
                float* dst = half ? b : a;
                int row = r0 + (pr * 2 + half) * 256;
                if (row < N) {
                    const float4* z4 = (const float4*)(zsrc + (size_t)row * C);
                    #pragma unroll
                    for (int k = 0; k < 8; k++) {
                        float4 v = z4[k];
                        dst[4*k] = v.x; dst[4*k+1] = v.y; dst[4*k+2] = v.z; dst[4*k+3] = v.w;
                    }
                } else {
                    #pragma unroll
                    for (int k = 0; k < C; k++) dst[k] = 0.f;
                }
                float s = 0.f;
                #pragma unroll
                for (int k = 0; k < C; k++) s = __fadd_rn(s, __fmul_rn(dst[k], dst[k]));
                z2[pr * 2 + half] = s;
            }
            ull* zz = pr ? zzB : zzA;
            #pragma unroll
            for (int c = 0; c < C; c++) zz[c] = pack2(a[c], b[c]);
        }
        z2A = pack2(z2[0], z2[1]);
        z2B = pack2(z2[2], z2[3]);
    }
    const ull neg2 = pack2(-2.f, -2.f);

    float best[4]; int bj[4];
    #pragma unroll
    for (int k = 0; k < 4; k++) { best[k] = FLT_MAX; bj[k] = 0; }

    int code0 = blockIdx.y * cpc;
    int T = cpc >> 6;

    {   // prime tile 0
        const ulonglong2* src = (const ulonglong2*)(g_embd + (size_t)code0 * C);
        ulonglong2* dst = (ulonglong2*)s_d[0];
        #pragma unroll
        for (int i = 0; i < 4; i++) dst[tid + 256 * i] = src[tid + 256 * i];
        if (tid < 32) ((ulonglong2*)s_q[0])[tid] = ((const ulonglong2*)(g_esqd + code0))[tid];
    }

    for (int t = 0; t < T; t++) {
        __syncthreads();
        if (t + 1 < T) {
            int cb = code0 + (t + 1) * 64;
            const ulonglong2* src = (const ulonglong2*)(g_embd + (size_t)cb * C);
            ulonglong2* dst = (ulonglong2*)s_d[(t + 1) & 1];
            #pragma unroll
            for (int i = 0; i < 4; i++) dst[tid + 256 * i] = src[tid + 256 * i];
            if (tid < 32)
                ((ulonglong2*)s_q[(t + 1) & 1])[tid] =
                    ((const ulonglong2*)(g_esqd + cb))[tid];
        }
        int bsel = t & 1;
        unsigned sb = (unsigned)__cvta_generic_to_shared(s_d[bsel]);
        const ull* sq = s_q[bsel];
        #pragma unroll 1
        for (int g = 0; g < 16; g++) {     // 4 codes per group
            ull acc[8];                    // [0..3]=rowpair A, [4..7]=rowpair B
            #pragma unroll
            for (int i = 0; i < 8; i++) acc[i] = 0ULL;
            unsigned ab = sb + (unsigned)g * 1024u;    // 4 codes x 32 ch x 8B
            #pragma unroll
            for (int c = 0; c < C; c += 2) {
                ull u0[4], u1[4];
                #pragma unroll
                for (int i = 0; i < 4; i++)
                    asm volatile("ld.shared.v2.b64 {%0,%1}, [%2];"
                                 : "=l"(u0[i]), "=l"(u1[i])
                                 : "r"(ab + (unsigned)i * 256u + (unsigned)c * 8u));
                #pragma unroll
                for (int i = 0; i < 4; i++)
                    asm("fma.rn.f32x2 %0, %1, %2, %0;" : "+l"(acc[i])   : "l"(zzA[c]),   "l"(u0[i]));
                #pragma unroll
                for (int i = 0; i < 4; i++)
                    asm("fma.rn.f32x2 %0, %1, %2, %0;" : "+l"(acc[4+i]) : "l"(zzB[c]),   "l"(u0[i]));
                #pragma unroll
                for (int i = 0; i < 4; i++)
                    asm("fma.rn.f32x2 %0, %1, %2, %0;" : "+l"(acc[i])   : "l"(zzA[c+1]), "l"(u1[i]));
                #pragma unroll
                for (int i = 0; i < 4; i++)
                    asm("fma.rn.f32x2 %0, %1, %2, %0;" : "+l"(acc[4+i]) : "l"(zzB[c+1]), "l"(u1[i]));
            }
            int jb = code0 + t * 64 + g * 4;
            #pragma unroll
            for (int i = 0; i < 4; i++) {
                ull qd = sq[g * 4 + i];
                ull tA, tB, sA, sB;
                asm("add.rn.f32x2 %0, %1, %2;" : "=l"(tA) : "l"(z2A), "l"(qd));
                asm("add.rn.f32x2 %0, %1, %2;" : "=l"(tB) : "l"(z2B), "l"(qd));
                asm("fma.rn.f32x2 %0, %1, %2, %3;" : "=l"(sA) : "l"(acc[i]),   "l"(neg2), "l"(tA));
                asm("fma.rn.f32x2 %0, %1, %2, %3;" : "=l"(sB) : "l"(acc[4+i]), "l"(neg2), "l"(tB));
                float s0, s1, s2, s3;
                asm("mov.b64 {%0,%1}, %2;" : "=f"(s0), "=f"(s1) : "l"(sA));
                asm("mov.b64 {%0,%1}, %2;" : "=f"(s2), "=f"(s3) : "l"(sB));
                int j = jb + i;
                if (s0 < best[0]) { best[0] = s0; bj[0] = j; }   // strict < : first-min
                if (s1 < best[1]) { best[1] = s1; bj[1] = j; }
                if (s2 < best[2]) { best[2] = s2; bj[2] = j; }
                if (s3 < best[3]) { best[3] = s3; bj[3] = j; }
            }
        }
    }
    #pragma unroll
    for (int k = 0; k < 4; k++) {
        int row = r0 + k * 256;
        if (row < N) {
            unsigned sbits = __float_as_uint(best[k]);
            sbits = (sbits & 0x80000000u) ? ~sbits : (sbits | 0x80000000u);
            ull key = ((ull)sbits << 32) | (unsigned)bj[k];
            atomicMin(&g_best[base + row], key);
        }
    }
}

// ---------------- gather + bicubic upsample (H then W) + residual update, float4 --------
__global__ void k_update(const float* __restrict__ emb, int si, int pn, int base) {
    int t = blockIdx.x * blockDim.x + threadIdx.x;     // 131072 threads
    if (t >= NPIX * 8) return;
    int c4 = t & 7; int ow = (t >> 3) & 15; int oh = (t >> 7) & 15; int b = t >> 11;
    int ih0 = g_upi[si][oh], iw0 = g_upi[si][ow];
    float4 acc = make_float4(0.f,0.f,0.f,0.f);
    #pragma unroll
    for (int d = 0; d < 4; d++) {             // W contraction (outer, second stage)
        int iw = iw0 + d;
        if (iw < 0 || iw >= pn) continue;
        float wv = g_upw[si][ow][d];
        float4 tc = make_float4(0.f,0.f,0.f,0.f);
        #pragma unroll
        for (int a = 0; a < 4; a++) {         // H contraction (inner, first stage)
            int ih = ih0 + a;
            if (ih < 0 || ih >= pn) continue;
            float wh = g_upw[si][oh][a];
            int j = (int)(unsigned)g_best[base + (b*pn + ih)*pn + iw];
            float4 e = __ldg((const float4*)emb + (size_t)j * 8 + c4);
            tc.x = fmaf(wh, e.x, tc.x); tc.y = fmaf(wh, e.y, tc.y);
            tc.z = fmaf(wh, e.z, tc.z); tc.w = fmaf(wh, e.w, tc.w);
        }
        acc.x = fmaf(wv, tc.x, acc.x); acc.y = fmaf(wv, tc.y, acc.y);
        acc.z = fmaf(wv, tc.z, acc.z); acc.w = fmaf(wv, tc.w, acc.w);
    }
    float4 fh = ((float4*)g_fhat)[t];
    float4 fr = ((float4*)g_frest)[t];
    fh.x = __fadd_rn(fh.x, acc.x); fh.y = __fadd_rn(fh.y, acc.y);
    fh.z = __fadd_rn(fh.z, acc.z); fh.w = __fadd_rn(fh.w, acc.w);
    fr.x = __fadd_rn(fr.x, -acc.x); fr.y = __fadd_rn(fr.y, -acc.y);
    fr.z = __fadd_rn(fr.z, -acc.z); fr.w = __fadd_rn(fr.w, -acc.w);
    ((float4*)g_fhat)[t]  = fh;
    ((float4*)g_frest)[t] = fr;
}

// ---------------- last scale: gather at full res + transpose to BCHW ----------------
__global__ void k_final(const float* __restrict__ emb, float* __restrict__ out, int base) {
    int t = blockIdx.x * blockDim.x + threadIdx.x;     // 131072 threads
    if (t >= NPIX * 8) return;
    int c4 = t & 7; int w = (t >> 3) & 15; int h = (t >> 7) & 15; int b = t >> 11;
    int j = (int)(unsigned)g_best[base + (b*HH + h)*WW + w];
    float4 fh = ((float4*)g_fhat)[t];
    float4 e  = __ldg((const float4*)emb + (size_t)j * 8 + c4);
    float* op = out + ((size_t)b*C + c4*4)*256 + h*WW + w;
    op[0]   = __fadd_rn(fh.x, e.x);
    op[256] = __fadd_rn(fh.y, e.y);
    op[512] = __fadd_rn(fh.z, e.z);
    op[768] = __fadd_rn(fh.w, e.w);
}

// ---------------- host ----------------
extern "C" void kernel_launch(void* const* d_in, const int* in_sizes, int n_in,
                              void* d_out, int out_size) {
    const float* f   = (const float*)d_in[0];
    const float* emb = (const float*)d_in[1];
    float* out = (float*)d_out;
    static const int PNS [10] = {1,2,3,4,5,6,8,10,13,16};
    static const int CHS [10] = {64,64,64,64,64,64,64,32,16,16};  // vocab chunks
    static const int BASE[10] = {0,64,320,896,1920,3520,5824,9920,16320,27136};

    k_init<<<512, 256>>>(f, emb);

    for (int si = 0; si < 10; si++) {
        int pn = PNS[si];
        int N  = B * pn * pn;
        int last = (si == 9);

        if (!last) {
            int tw = N * 8;
            k_pool<<<(tw + 255)/256, 256>>>(pn, tw);
        }

        int bx = (N + 1023) / 1024;
        int CH = CHS[si];
        k_argmin<<<dim3(bx, CH), 256>>>(N, last ? 1 : 0, VOCAB / CH, BASE[si]);

        if (!last) k_update<<<512, 256>>>(emb, si, pn, BASE[si]);
        else       k_final <<<512, 256>>>(emb, out, BASE[si]);
    }
}